// round 3
// baseline (speedup 1.0000x reference)
#include <cuda_runtime.h>

#define DD     4096
#define KB     128
#define TROWS  16384
#define NTHR   1024
#define RPB    4                  // rows per batch
#define NBATCH 4                  // batches per CTA
#define RPC    (RPB * NBATCH)     // 16 rows per CTA
#define NBLK   (TROWS / RPC)

__device__ int            g_offsets[KB + 1];
__device__ unsigned short g_perm[DD];

// ---------------------------------------------------------------------------
// K0: deterministic counting sort via __match_any ranks (no atomics, no
// serial placement). Order within a bin = j ascending -> bitwise deterministic.
// ---------------------------------------------------------------------------
__global__ void __launch_bounds__(1024)
k0_build(const int* __restrict__ assign) {
    __shared__ unsigned short s_cnt[KB * 128];   // [bin][round], 32 KB
    __shared__ int s_warp[32];
    const int tid = threadIdx.x, lane = tid & 31, w = tid >> 5;

    int av[4];
    #pragma unroll
    for (int i = 0; i < 4; i++) av[i] = assign[tid + 1024 * i] & 127;

    for (int c2 = tid; c2 < KB * 128 / 2; c2 += 1024) ((unsigned*)s_cnt)[c2] = 0;
    __syncthreads();

    // round(j) = j>>5 : j = tid + 1024*i -> round = w + 32*i, lane = tid&31
    unsigned rank[4];
    #pragma unroll
    for (int i = 0; i < 4; i++) {
        unsigned mask = __match_any_sync(0xffffffffu, av[i]);
        rank[i] = __popc(mask & ((1u << lane) - 1u));
        if (rank[i] == 0)   // lowest lane of the match group
            s_cnt[av[i] * 128 + (w + 32 * i)] = (unsigned short)__popc(mask);
    }
    __syncthreads();

    // exclusive scan of 16384 cells in (bin, round) order; 16 cells/thread
    int loc[16], sum = 0;
    const int base = tid * 16;
    #pragma unroll
    for (int u = 0; u < 16; u++) { loc[u] = s_cnt[base + u]; sum += loc[u]; }
    int v = sum;
    #pragma unroll
    for (int d = 1; d < 32; d <<= 1) {
        int n = __shfl_up_sync(0xffffffffu, v, d);
        if (lane >= d) v += n;
    }
    if (lane == 31) s_warp[w] = v;
    __syncthreads();
    if (w == 0) {
        int t = s_warp[lane];
        #pragma unroll
        for (int d = 1; d < 32; d <<= 1) {
            int n = __shfl_up_sync(0xffffffffu, t, d);
            if (lane >= d) t += n;
        }
        s_warp[lane] = t;
    }
    __syncthreads();
    int run = v - sum + (w > 0 ? s_warp[w - 1] : 0);
    #pragma unroll
    for (int u = 0; u < 16; u++) {
        int c = loc[u]; s_cnt[base + u] = (unsigned short)run; run += c;
    }
    __syncthreads();

    if (tid < KB) g_offsets[tid] = s_cnt[tid * 128];
    if (tid == 0) g_offsets[KB]  = DD;

    #pragma unroll
    for (int i = 0; i < 4; i++) {
        int pos = (int)s_cnt[av[i] * 128 + (w + 32 * i)] + (int)rank[i];
        g_perm[pos] = (unsigned short)(tid + 1024 * i);
    }
}

// ---------------------------------------------------------------------------
// Fused main kernel: per 4-row batch
//   stage x^T (4 rows interleaved, swizzled)  ->  y[128] bin sums (LDS.128 x4 rows)
//   qm = y @ QV via packed fma.rn.f32x2       ->  out = qm4[a_j] + bias (LDS.128 x4 rows)
// ---------------------------------------------------------------------------
__device__ __forceinline__ int swz(int j) { return j ^ ((j >> 3) & 7); }

__device__ __forceinline__ void fma2(unsigned long long& d,
                                     unsigned long long a, unsigned long long b) {
    asm("fma.rn.f32x2 %0, %1, %2, %0;" : "+l"(d) : "l"(a), "l"(b));
}
__device__ __forceinline__ unsigned long long pack2(float q) {
    unsigned long long r;
    asm("mov.b64 %0, {%1, %1};" : "=l"(r) : "r"(__float_as_uint(q)));
    return r;
}

#define OFF_PERM  65536
#define OFF_PART  (65536 + 8192)
#define OFF_Y     (OFF_PART + 16384)
#define OFF_QM    (OFF_Y + 2048)
#define OFF_OFF   (OFF_QM + 2048)
#define SMEM_BYTES (OFF_OFF + 4 * (KB + 1))

__global__ void __launch_bounds__(NTHR, 1)
vq_fused(const float* __restrict__ x, const float* __restrict__ qv,
         const int* __restrict__ assign, const float* __restrict__ bias,
         float* __restrict__ out) {
    extern __shared__ char smem[];
    float4*         s_x4   = (float4*)smem;                 // [4096] 64 KB
    unsigned short* s_perm = (unsigned short*)(smem + OFF_PERM);
    float4*         s_part = (float4*)(smem + OFF_PART);    // [1024] 16 KB
    float4*         s_y4   = (float4*)(smem + OFF_Y);       // [128]
    float4*         s_qm4  = (float4*)(smem + OFF_QM);      // [128]
    int*            s_off  = (int*)(smem + OFF_OFF);

    const int tid = threadIdx.x;

    for (int i = tid; i < DD / 2; i += NTHR)
        ((unsigned*)s_perm)[i] = ((const unsigned*)g_perm)[i];
    if (tid <= KB) s_off[tid] = g_offsets[tid];

    // matvec mapping: thread covers k_out = kout, k_in in [c*16, c*16+16)
    const int kout = tid & 127, c = tid >> 7;
    float qreg[16];
    #pragma unroll
    for (int i = 0; i < 16; i++) qreg[i] = qv[(c * 16 + i) * KB + kout];

    // output mapping: thread owns float4 slot tid (features 4tid..4tid+3)
    const float4 biasr = ((const float4*)bias)[tid];
    const int4 a4i = ((const int4*)assign)[tid];
    const unsigned ar = (unsigned)(a4i.x & 127)
                      | ((unsigned)(a4i.y & 127) << 8)
                      | ((unsigned)(a4i.z & 127) << 16)
                      | ((unsigned)(a4i.w & 127) << 24);

    const int t0 = blockIdx.x * RPC;
    const float4* x4   = (const float4*)x;
    float4*       out4 = (float4*)out;

    float4 v[4];
    #pragma unroll
    for (int r = 0; r < 4; r++) v[r] = x4[(size_t)(t0 + r) * 1024 + tid];

    __syncthreads();
    const int bin = tid >> 3, sub = tid & 7;
    const int lo = s_off[bin] + sub, hi = s_off[bin + 1];

    #pragma unroll 1
    for (int b = 0; b < NBATCH; b++) {
        const int tb = t0 + b * RPB;

        // stage: s_x4[j] = {x[tb..tb+3][j]}  (4x4 register transpose)
        s_x4[swz(4 * tid + 0)] = make_float4(v[0].x, v[1].x, v[2].x, v[3].x);
        s_x4[swz(4 * tid + 1)] = make_float4(v[0].y, v[1].y, v[2].y, v[3].y);
        s_x4[swz(4 * tid + 2)] = make_float4(v[0].z, v[1].z, v[2].z, v[3].z);
        s_x4[swz(4 * tid + 3)] = make_float4(v[0].w, v[1].w, v[2].w, v[3].w);

        if (b + 1 < NBATCH) {   // prefetch next batch; hidden under compute
            #pragma unroll
            for (int r = 0; r < 4; r++)
                v[r] = x4[(size_t)(tb + RPB + r) * 1024 + tid];
        }
        __syncthreads();

        // bin gather: one LDS.128 = feature j for 4 rows
        float4 acc = make_float4(0.f, 0.f, 0.f, 0.f);
        for (int s = lo; s < hi; s += 8) {
            float4 xv = s_x4[swz((int)s_perm[s])];
            acc.x += xv.x; acc.y += xv.y; acc.z += xv.z; acc.w += xv.w;
        }
        s_part[bin * 8 + (sub ^ (bin & 7))] = acc;
        __syncthreads();

        if (tid < KB) {
            float4 t = make_float4(0.f, 0.f, 0.f, 0.f);
            #pragma unroll
            for (int u = 0; u < 8; u++) {
                float4 p = s_part[tid * 8 + (u ^ (tid & 7))];
                t.x += p.x; t.y += p.y; t.z += p.z; t.w += p.w;
            }
            s_y4[tid] = t;   // y for 4 rows
        }
        __syncthreads();

        // matvec: qm[rows 0..3][kout], packed f32x2 over row pairs
        const ulonglong2* sy2 = (const ulonglong2*)s_y4;
        unsigned long long acc01 = 0ull, acc23 = 0ull;
        #pragma unroll
        for (int i = 0; i < 16; i++) {
            ulonglong2 yv = sy2[c * 16 + i];        // broadcast within warp
            unsigned long long qd = pack2(qreg[i]);
            fma2(acc01, yv.x, qd);
            fma2(acc23, yv.y, qd);
        }
        ((ulonglong2*)s_part)[kout * 8 + (c ^ (kout & 7))] =
            make_ulonglong2(acc01, acc23);
        __syncthreads();

        if (tid < KB) {
            float4 t = make_float4(0.f, 0.f, 0.f, 0.f);
            #pragma unroll
            for (int u = 0; u < 8; u++) {
                float4 p = s_part[tid * 8 + (u ^ (tid & 7))];
                t.x += p.x; t.y += p.y; t.z += p.z; t.w += p.w;
            }
            s_qm4[tid] = t;
        }
        __syncthreads();

        // epilogue: 4 random LDS.128 serve 4 rows x 4 features
        float4 q0 = s_qm4[ar & 255];
        float4 q1 = s_qm4[(ar >> 8)  & 255];
        float4 q2 = s_qm4[(ar >> 16) & 255];
        float4 q3 = s_qm4[(ar >> 24)];
        size_t rb = (size_t)tb * 1024 + tid;
        out4[rb]          = make_float4(q0.x + biasr.x, q1.x + biasr.y, q2.x + biasr.z, q3.x + biasr.w);
        out4[rb + 1024]   = make_float4(q0.y + biasr.x, q1.y + biasr.y, q2.y + biasr.z, q3.y + biasr.w);
        out4[rb + 2048]   = make_float4(q0.z + biasr.x, q1.z + biasr.y, q2.z + biasr.z, q3.z + biasr.w);
        out4[rb + 3072]   = make_float4(q0.w + biasr.x, q1.w + biasr.y, q2.w + biasr.z, q3.w + biasr.w);

        __syncthreads();   // s_qm4/s_part consumed before next batch reuses
    }
}

extern "C" void kernel_launch(void* const* d_in, const int* in_sizes, int n_in,
                              void* d_out, int out_size) {
    const float* x      = (const float*)d_in[0];
    const float* qv     = (const float*)d_in[1];
    const int*   assign = (const int*)d_in[2];
    const float* bias   = (const float*)d_in[3];
    float*       out    = (float*)d_out;

    (void)cudaFuncSetAttribute(vq_fused,
                               cudaFuncAttributeMaxDynamicSharedMemorySize,
                               SMEM_BYTES);

    k0_build<<<1, 1024>>>(assign);
    vq_fused<<<NBLK, NTHR, SMEM_BYTES>>>(x, qv, assign, bias, out);
}